// round 13
// baseline (speedup 1.0000x reference)
#include <cuda_runtime.h>
#include <cuda_fp16.h>
#include <cstdint>

// ---------------------------------------------------------------------------
// Problem constants
// ---------------------------------------------------------------------------
#define BSZ      4
#define SEQ      4096
#define EMB      1024
#define HID      2048
#define FOURH    8192
#define MROWS    (BSZ*SEQ)      // 16384
#define NCH      (BSZ*HID)      // 8192 scan channels

// GEMM tile config (HMMA mma.sync — tcgen05 unavailable at .target sm_103)
#define BM 128
#define BN 128
#define BKK 64
#define ROWB 144                        // 128B data + 16B pad
#define A_MAT (128*ROWB)                // 18432
#define STAGE (2*A_MAT)                 // 36864
#define NSTAGE 3
#define SMEMG (NSTAGE*STAGE)            // 110592/CTA, 2 CTAs/SM
#define GTHREADS 128

// ---------------------------------------------------------------------------
// Scratch (static device globals)
// ---------------------------------------------------------------------------
__device__ float g_y [(size_t)MROWS * FOURH];
__device__ float g_a [(size_t)NCH   * SEQ];
__device__ float g_b [(size_t)NCH   * SEQ];
__device__ float g_hs[(size_t)NCH   * SEQ];
__device__ __half g_xh [(size_t)MROWS * EMB];
__device__ __half g_w1h[(size_t)FOURH * EMB];
__device__ __half g_w2h[(size_t)EMB * HID];
__device__ __half g_gh [(size_t)MROWS * HID];

// ---------------------------------------------------------------------------
// PTX helpers (sm_80-baseline)
// ---------------------------------------------------------------------------
__device__ __forceinline__ uint32_t smem_u32(const void* p) {
    uint32_t a;
    asm("{ .reg .u64 t; cvta.to.shared.u64 t, %1; cvt.u32.u64 %0, t; }" : "=r"(a) : "l"(p));
    return a;
}
__device__ __forceinline__ void cp16(uint32_t s, const void* g) {
    asm volatile("cp.async.cg.shared.global [%0], [%1], 16;" :: "r"(s), "l"(g));
}
#define CP_COMMIT() asm volatile("cp.async.commit_group;" ::: "memory")
#define CP_WAIT(n)  asm volatile("cp.async.wait_group %0;" :: "n"(n) : "memory")

__device__ __forceinline__ void ldsm4(uint32_t* r, uint32_t addr) {
    asm volatile("ldmatrix.sync.aligned.m8n8.x4.shared.b16 {%0,%1,%2,%3}, [%4];"
                 : "=r"(r[0]), "=r"(r[1]), "=r"(r[2]), "=r"(r[3]) : "r"(addr));
}
__device__ __forceinline__ void mma16816(float* c, const uint32_t* a, uint32_t b0, uint32_t b1) {
    asm volatile(
        "mma.sync.aligned.m16n8k16.row.col.f32.f16.f16.f32 "
        "{%0,%1,%2,%3}, {%4,%5,%6,%7}, {%8,%9}, {%0,%1,%2,%3};"
        : "+f"(c[0]), "+f"(c[1]), "+f"(c[2]), "+f"(c[3])
        : "r"(a[0]), "r"(a[1]), "r"(a[2]), "r"(a[3]), "r"(b0), "r"(b1));
}

// ---------------------------------------------------------------------------
// fp32 -> fp16 round
// ---------------------------------------------------------------------------
__global__ __launch_bounds__(256)
void round1_kernel(const float* __restrict__ in, __half* __restrict__ out, int n4)
{
    int i = blockIdx.x * 256 + threadIdx.x;
    if (i >= n4) return;
    float4 v = ((const float4*)in)[i];
    __half2* op = (__half2*)out;
    op[2*i]   = __half2(__float2half_rn(v.x), __float2half_rn(v.y));
    op[2*i+1] = __half2(__float2half_rn(v.z), __float2half_rn(v.w));
}

// ---------------------------------------------------------------------------
// HMMA fp16 GEMM: C[M,N] = A[M,K] @ B[N,K]^T.
// CTA tile 128x128, BK=64, 3-stage cp.async pipeline (1 sync/iter),
// 128 threads (4 warps), warp grid 2x2, warp tile 64x64, 2 CTAs/SM,
// explicit ks-level fragment pipelining.
// ---------------------------------------------------------------------------
__global__ __launch_bounds__(GTHREADS, 2)
void gemm_hmma_kernel(const __half* __restrict__ Ah,
                      const __half* __restrict__ Bh,
                      float* __restrict__ C, int N, int K)
{
    extern __shared__ char smem[];
    const uint32_t sbase = smem_u32(smem);
    const int tid  = threadIdx.x;
    const int wid  = tid >> 5;
    const int lane = tid & 31;
    const int bm = blockIdx.y * BM;
    const int bn = blockIdx.x * BN;
    const int wm = (wid >> 1) * 64;
    const int wn = (wid & 1) * 64;

    const int NC = K / BKK;

    const int lrow = tid >> 3;          // 0..15
    const int lch  = tid & 7;           // 0..7
    auto load_stage = [&](int kc, int buf) {
        const uint32_t sb = sbase + buf * STAGE;
        const int k0 = kc * BKK;
#pragma unroll
        for (int j = 0; j < 8; j++) {
            int r = lrow + j * 16;
            size_t goA = (size_t)(bm + r) * K + k0 + lch * 8;
            size_t goB = (size_t)(bn + r) * K + k0 + lch * 8;
            uint32_t so = sb + r * ROWB + lch * 16;
            cp16(so,         Ah + goA);
            cp16(so + A_MAT, Bh + goB);
        }
    };

    // ldmatrix lane addressing
    const int lr  = lane & 7;
    const int sel = lane >> 3;
    const uint32_t a_lane_off = (uint32_t)((wm + lr + ((sel & 1) << 3)) * ROWB + ((sel >> 1) << 4));
    const uint32_t b_lane_off = (uint32_t)(A_MAT + (wn + lr + ((sel >> 1) << 3)) * ROWB + ((sel & 1) << 4));

    float acc[4][8][4];
#pragma unroll
    for (int mt = 0; mt < 4; mt++)
#pragma unroll
        for (int nt = 0; nt < 8; nt++)
#pragma unroll
            for (int r = 0; r < 4; r++) acc[mt][nt][r] = 0.f;

    load_stage(0, 0); CP_COMMIT();
    load_stage(1, 1); CP_COMMIT();

    int buf = 0;
    for (int it = 0; it < NC; it++) {
        if (it + 1 < NC) { CP_WAIT(1); } else { CP_WAIT(0); }
        __syncthreads();

        if (it + 2 < NC) { load_stage(it + 2, (buf + 2) % NSTAGE); CP_COMMIT(); }

        const uint32_t sb = sbase + buf * STAGE;

        // fragment double buffers: ks-level software pipeline
        uint32_t acur[4][4], bcur[4][4], anxt[4][4], bnxt[4][4];
#pragma unroll
        for (int mt = 0; mt < 4; mt++)
            ldsm4(acur[mt], sb + a_lane_off + mt * (16 * ROWB));
#pragma unroll
        for (int ng = 0; ng < 4; ng++)
            ldsm4(bcur[ng], sb + b_lane_off + ng * (16 * ROWB));

#pragma unroll
        for (int ks = 0; ks < 4; ks++) {
            if (ks < 3) {
                const uint32_t kofs = (ks + 1) * 32;
#pragma unroll
                for (int mt = 0; mt < 4; mt++)
                    ldsm4(anxt[mt], sb + a_lane_off + mt * (16 * ROWB) + kofs);
#pragma unroll
                for (int ng = 0; ng < 4; ng++)
                    ldsm4(bnxt[ng], sb + b_lane_off + ng * (16 * ROWB) + kofs);
            }
#pragma unroll
            for (int ng = 0; ng < 4; ng++) {
#pragma unroll
                for (int mt = 0; mt < 4; mt++) {
                    mma16816(acc[mt][ng * 2 + 0], acur[mt], bcur[ng][0], bcur[ng][1]);
                    mma16816(acc[mt][ng * 2 + 1], acur[mt], bcur[ng][2], bcur[ng][3]);
                }
            }
            if (ks < 3) {
#pragma unroll
                for (int mt = 0; mt < 4; mt++)
#pragma unroll
                    for (int q = 0; q < 4; q++) acur[mt][q] = anxt[mt][q];
#pragma unroll
                for (int ng = 0; ng < 4; ng++)
#pragma unroll
                    for (int q = 0; q < 4; q++) bcur[ng][q] = bnxt[ng][q];
            }
        }
        buf = (buf + 1) % NSTAGE;
    }

    // Epilogue: direct fp32 stores
    const int rrow = lane >> 2;
    const int rcol = (lane & 3) * 2;
#pragma unroll
    for (int mt = 0; mt < 4; mt++) {
        const int row0 = bm + wm + mt * 16 + rrow;
#pragma unroll
        for (int nt = 0; nt < 8; nt++) {
            const int col = bn + wn + nt * 8 + rcol;
            *(float2*)(C + (size_t)row0 * N + col)       = make_float2(acc[mt][nt][0], acc[mt][nt][1]);
            *(float2*)(C + (size_t)(row0 + 8) * N + col) = make_float2(acc[mt][nt][2], acc[mt][nt][3]);
        }
    }
}

// ---------------------------------------------------------------------------
// Conv + gates, rolling-window: each thread owns channel c and 32 timesteps.
// grid: (HID/32, SEQ/256, BSZ), block (32, 8).
// Outputs channel-major [C, S]; per-thread contiguous 128B-row writes.
// ---------------------------------------------------------------------------
__global__ __launch_bounds__(256)
void conv_gate_kernel(const float* __restrict__ cw)
{
    const int c  = blockIdx.x * 32 + threadIdx.x;
    const int fc = ((c >> 7) << 8) | (c & 127);
    const int ic = fc + 128;
    const int b  = blockIdx.z;
    const int t0 = (blockIdx.y * 8 + threadIdx.y) * 32;

    float wf[4], wi[4];
#pragma unroll
    for (int k = 0; k < 4; k++) { wf[k] = cw[fc * 4 + k]; wi[k] = cw[ic * 4 + k]; }

    const float* yf = g_y + (size_t)(b * SEQ) * FOURH + 4096 + fc;
    const float* yi = g_y + (size_t)(b * SEQ) * FOURH + 4096 + ic;
    const float* yh = g_y + (size_t)(b * SEQ) * FOURH + 2048 + c;

    // rolling history: x[t-3], x[t-2], x[t-1]
    float f0 = 0.f, f1 = 0.f, f2 = 0.f;
    float i0 = 0.f, i1 = 0.f, i2 = 0.f;
#pragma unroll
    for (int j = 0; j < 3; j++) {
        int tp = t0 - 3 + j;
        float vf = 0.f, vi = 0.f;
        if (tp >= 0) { vf = yf[(size_t)tp * FOURH]; vi = yi[(size_t)tp * FOURH]; }
        if (j == 0) { f0 = vf; i0 = vi; }
        if (j == 1) { f1 = vf; i1 = vi; }
        if (j == 2) { f2 = vf; i2 = vi; }
    }

    float oa[32], ob[32];
#pragma unroll
    for (int j = 0; j < 32; j++) {
        const int t = t0 + j;
        const float vf = yf[(size_t)t * FOURH];
        const float vi = yi[(size_t)t * FOURH];
        const float h  = yh[(size_t)t * FOURH];
        const float accf = wf[0]*f0 + wf[1]*f1 + wf[2]*f2 + wf[3]*vf;
        const float acci = wi[0]*i0 + wi[1]*i1 + wi[2]*i2 + wi[3]*vi;
        f0 = f1; f1 = f2; f2 = vf;
        i0 = i1; i1 = i2; i2 = vi;
        const float f = 1.f / (1.f + __expf(-accf));
        const float i = 1.f / (1.f + __expf(-acci));
        const float denom = 1.f / (f + i + 1e-4f);
        oa[j] = f * denom;
        ob[j] = h * i * denom;
    }

    const size_t obase = (size_t)(b * HID + c) * SEQ + t0;
#pragma unroll
    for (int j = 0; j < 32; j += 4) {
        *(float4*)(g_a + obase + j) = make_float4(oa[j], oa[j+1], oa[j+2], oa[j+3]);
        *(float4*)(g_b + obase + j) = make_float4(ob[j], ob[j+1], ob[j+2], ob[j+3]);
    }
}

// ---------------------------------------------------------------------------
// Linear scan per channel
// ---------------------------------------------------------------------------
__global__ __launch_bounds__(128)
void scan_kernel()
{
    const int ch  = blockIdx.x;
    const int tid = threadIdx.x;
    const size_t base = (size_t)ch * SEQ + (size_t)tid * 32;

    float a[32], bb[32];
#pragma unroll
    for (int j = 0; j < 32; j += 4) {
        float4 va = *(const float4*)(g_a + base + j);
        float4 vb = *(const float4*)(g_b + base + j);
        a[j+0]=va.x; a[j+1]=va.y; a[j+2]=va.z; a[j+3]=va.w;
        bb[j+0]=vb.x; bb[j+1]=vb.y; bb[j+2]=vb.z; bb[j+3]=vb.w;
    }

    float A = 1.f, Bv = 0.f;
#pragma unroll
    for (int j = 0; j < 32; j++) { Bv = fmaf(a[j], Bv, bb[j]); A *= a[j]; }

    __shared__ float sA[128], sB[128];
    sA[tid] = A; sB[tid] = Bv;
    __syncthreads();
    for (int off = 1; off < 128; off <<= 1) {
        float pA = 0.f, pB = 0.f;
        if (tid >= off) { pA = sA[tid - off]; pB = sB[tid - off]; }
        __syncthreads();
        if (tid >= off) { Bv = fmaf(A, pB, Bv); A = A * pA; sA[tid] = A; sB[tid] = Bv; }
        __syncthreads();
    }

    float h = (tid == 0) ? 0.f : sB[tid - 1];
#pragma unroll
    for (int j = 0; j < 32; j++) { h = fmaf(a[j], h, bb[j]); bb[j] = h; }
#pragma unroll
    for (int j = 0; j < 32; j += 4)
        *(float4*)(g_hs + base + j) = make_float4(bb[j], bb[j+1], bb[j+2], bb[j+3]);
}

// ---------------------------------------------------------------------------
// g = silu(out1) * out2 ; writes fp16 for GEMM2
// ---------------------------------------------------------------------------
__global__ __launch_bounds__(256)
void silu_mul_kernel()
{
    __shared__ float sm[32][33];
    const int c0 = blockIdx.x * 32;
    const int s0 = blockIdx.y * 32;
    const int b  = blockIdx.z;

#pragma unroll
    for (int it = 0; it < 4; ++it) {
        const int cl = threadIdx.y + it * 8;
        const int s  = s0 + threadIdx.x;
        sm[cl][threadIdx.x] = g_hs[((size_t)(b * HID + c0 + cl)) * SEQ + s];
    }
    __syncthreads();

#pragma unroll
    for (int it = 0; it < 4; ++it) {
        const int sl = threadIdx.y + it * 8;
        const int s  = s0 + sl;
        const int c  = c0 + threadIdx.x;
        const size_t row = (size_t)(b * SEQ + s);
        const float o1 = g_y[row * FOURH + c];
        const float sil = o1 / (1.f + __expf(-o1));
        const float v = sil * sm[threadIdx.x][sl];
        g_gh[row * HID + c] = __float2half_rn(v);
    }
}

// ---------------------------------------------------------------------------
// Launch
// ---------------------------------------------------------------------------
extern "C" void kernel_launch(void* const* d_in, const int* in_sizes, int n_in,
                              void* d_out, int out_size)
{
    const float* x  = (const float*)d_in[0];
    const float* w1 = (const float*)d_in[1];
    const float* w2 = (const float*)d_in[2];
    const float* cw = (const float*)d_in[3];
    float* out = (float*)d_out;

    float *yp;
    cudaGetSymbolAddress((void**)&yp, g_y);
    __half *xh, *w1h, *w2h, *gh;
    cudaGetSymbolAddress((void**)&xh,  g_xh);
    cudaGetSymbolAddress((void**)&w1h, g_w1h);
    cudaGetSymbolAddress((void**)&w2h, g_w2h);
    cudaGetSymbolAddress((void**)&gh,  g_gh);

    cudaFuncSetAttribute(gemm_hmma_kernel, cudaFuncAttributeMaxDynamicSharedMemorySize, SMEMG);

    // conversions
    {
        int n4 = MROWS * EMB / 4;
        round1_kernel<<<(n4 + 255) / 256, 256>>>(x, xh, n4);
        n4 = FOURH * EMB / 4;
        round1_kernel<<<(n4 + 255) / 256, 256>>>(w1, w1h, n4);
        n4 = EMB * HID / 4;
        round1_kernel<<<(n4 + 255) / 256, 256>>>(w2, w2h, n4);
    }

    // GEMM1: y[M,8192] = x @ w1^T
    gemm_hmma_kernel<<<dim3(FOURH / BN, MROWS / BM), GTHREADS, SMEMG>>>(
        xh, w1h, yp, FOURH, EMB);

    conv_gate_kernel<<<dim3(HID / 32, SEQ / 256, BSZ), dim3(32, 8)>>>(cw);
    scan_kernel<<<NCH, 128>>>();
    silu_mul_kernel<<<dim3(HID / 32, SEQ / 32, BSZ), dim3(32, 8)>>>();

    // GEMM2: out[M,1024] = g @ w2^T
    gemm_hmma_kernel<<<dim3(EMB / BN, MROWS / BM), GTHREADS, SMEMG>>>(
        gh, w2h, out, EMB, HID);
}

// round 14
// speedup vs baseline: 1.1467x; 1.1467x over previous
#include <cuda_runtime.h>
#include <cuda_fp16.h>
#include <cstdint>

// ---------------------------------------------------------------------------
// Problem constants
// ---------------------------------------------------------------------------
#define BSZ      4
#define SEQ      4096
#define EMB      1024
#define HID      2048
#define FOURH    8192
#define MROWS    (BSZ*SEQ)      // 16384
#define NCH      (BSZ*HID)      // 8192 scan channels

// GEMM tile config (HMMA mma.sync — tcgen05 unavailable at .target sm_103)
#define BM 128
#define BN 128
#define BKK 64
#define ROWB 144                        // 128B data + 16B pad
#define A_MAT (128*ROWB)                // 18432
#define STAGE (2*A_MAT)                 // 36864
#define NSTAGE 3
#define SMEMG (NSTAGE*STAGE)            // 110592/CTA, 2 CTAs/SM
#define GTHREADS 128

// ---------------------------------------------------------------------------
// Scratch (static device globals)
// ---------------------------------------------------------------------------
__device__ float g_y [(size_t)MROWS * FOURH];
__device__ float g_a [(size_t)NCH   * SEQ];
__device__ float g_b [(size_t)NCH   * SEQ];
__device__ float g_hs[(size_t)NCH   * SEQ];
__device__ __half g_xh [(size_t)MROWS * EMB];
__device__ __half g_w1h[(size_t)FOURH * EMB];
__device__ __half g_w2h[(size_t)EMB * HID];
__device__ __half g_gh [(size_t)MROWS * HID];

// ---------------------------------------------------------------------------
// PTX helpers (sm_80-baseline)
// ---------------------------------------------------------------------------
__device__ __forceinline__ uint32_t smem_u32(const void* p) {
    uint32_t a;
    asm("{ .reg .u64 t; cvta.to.shared.u64 t, %1; cvt.u32.u64 %0, t; }" : "=r"(a) : "l"(p));
    return a;
}
__device__ __forceinline__ void cp16(uint32_t s, const void* g) {
    asm volatile("cp.async.cg.shared.global [%0], [%1], 16;" :: "r"(s), "l"(g));
}
#define CP_COMMIT() asm volatile("cp.async.commit_group;" ::: "memory")
#define CP_WAIT(n)  asm volatile("cp.async.wait_group %0;" :: "n"(n) : "memory")

__device__ __forceinline__ void ldsm4(uint32_t& r0, uint32_t& r1, uint32_t& r2, uint32_t& r3,
                                      uint32_t addr) {
    asm volatile("ldmatrix.sync.aligned.m8n8.x4.shared.b16 {%0,%1,%2,%3}, [%4];"
                 : "=r"(r0), "=r"(r1), "=r"(r2), "=r"(r3) : "r"(addr));
}
__device__ __forceinline__ void mma16816(float* c, uint32_t a0, uint32_t a1, uint32_t a2,
                                         uint32_t a3, uint32_t b0, uint32_t b1) {
    asm volatile(
        "mma.sync.aligned.m16n8k16.row.col.f32.f16.f16.f32 "
        "{%0,%1,%2,%3}, {%4,%5,%6,%7}, {%8,%9}, {%0,%1,%2,%3};"
        : "+f"(c[0]), "+f"(c[1]), "+f"(c[2]), "+f"(c[3])
        : "r"(a0), "r"(a1), "r"(a2), "r"(a3), "r"(b0), "r"(b1));
}

// ---------------------------------------------------------------------------
// Fused fp32 -> fp16 round over x | w1 | w2 (consecutive ranges)
// ---------------------------------------------------------------------------
__global__ __launch_bounds__(256)
void round_all_kernel(const float* __restrict__ x,  __half* __restrict__ xh,  int nx4,
                      const float* __restrict__ w1, __half* __restrict__ w1h, int n14,
                      const float* __restrict__ w2, __half* __restrict__ w2h, int n24)
{
    int i = blockIdx.x * 256 + threadIdx.x;
    const float* in; __half* out; int idx;
    if (i < nx4) { in = x; out = xh; idx = i; }
    else if (i < nx4 + n14) { in = w1; out = w1h; idx = i - nx4; }
    else if (i < nx4 + n14 + n24) { in = w2; out = w2h; idx = i - nx4 - n14; }
    else return;
    float4 v = ((const float4*)in)[idx];
    __half2* op = (__half2*)out;
    op[2*idx]   = __half2(__float2half_rn(v.x), __float2half_rn(v.y));
    op[2*idx+1] = __half2(__float2half_rn(v.z), __float2half_rn(v.w));
}

// ---------------------------------------------------------------------------
// HMMA fp16 GEMM: C[M,N] = A[M,K] @ B[N,K]^T.
// CTA tile 128x128, BK=64, 3-stage cp.async pipeline (1 sync/iter),
// 128 threads (4 warps), warp grid 2x2, warp tile 64x64, 2 CTAs/SM.
// (Exact R11 version — best measured.)
// ---------------------------------------------------------------------------
__global__ __launch_bounds__(GTHREADS, 2)
void gemm_hmma_kernel(const __half* __restrict__ Ah,
                      const __half* __restrict__ Bh,
                      float* __restrict__ C, int N, int K)
{
    extern __shared__ char smem[];
    const uint32_t sbase = smem_u32(smem);
    const int tid  = threadIdx.x;
    const int wid  = tid >> 5;
    const int lane = tid & 31;
    const int bm = blockIdx.y * BM;
    const int bn = blockIdx.x * BN;
    const int wm = (wid >> 1) * 64;
    const int wn = (wid & 1) * 64;

    const int NC = K / BKK;

    const int lrow = tid >> 3;          // 0..15
    const int lch  = tid & 7;           // 0..7
    auto load_stage = [&](int kc, int buf) {
        const uint32_t sb = sbase + buf * STAGE;
        const int k0 = kc * BKK;
#pragma unroll
        for (int j = 0; j < 8; j++) {
            int r = lrow + j * 16;
            size_t goA = (size_t)(bm + r) * K + k0 + lch * 8;
            size_t goB = (size_t)(bn + r) * K + k0 + lch * 8;
            uint32_t so = sb + r * ROWB + lch * 16;
            cp16(so,         Ah + goA);
            cp16(so + A_MAT, Bh + goB);
        }
    };

    // ldmatrix lane addressing
    const int lr  = lane & 7;
    const int sel = lane >> 3;
    const uint32_t a_lane_off = (uint32_t)((wm + lr + ((sel & 1) << 3)) * ROWB + ((sel >> 1) << 4));
    const uint32_t b_lane_off = (uint32_t)(A_MAT + (wn + lr + ((sel >> 1) << 3)) * ROWB + ((sel & 1) << 4));

    float acc[4][8][4];
#pragma unroll
    for (int mt = 0; mt < 4; mt++)
#pragma unroll
        for (int nt = 0; nt < 8; nt++)
#pragma unroll
            for (int r = 0; r < 4; r++) acc[mt][nt][r] = 0.f;

    load_stage(0, 0); CP_COMMIT();
    load_stage(1, 1); CP_COMMIT();

    int buf = 0;
    for (int it = 0; it < NC; it++) {
        if (it + 1 < NC) { CP_WAIT(1); } else { CP_WAIT(0); }
        __syncthreads();

        if (it + 2 < NC) { load_stage(it + 2, (buf + 2) % NSTAGE); CP_COMMIT(); }

        const uint32_t sb = sbase + buf * STAGE;
#pragma unroll
        for (int ks = 0; ks < 4; ks++) {
            const uint32_t kofs = ks * 32;
            uint32_t ah[4][4];
#pragma unroll
            for (int mt = 0; mt < 4; mt++) {
                uint32_t addr = sb + a_lane_off + mt * (16 * ROWB) + kofs;
                ldsm4(ah[mt][0], ah[mt][1], ah[mt][2], ah[mt][3], addr);
            }
#pragma unroll
            for (int ng = 0; ng < 4; ng++) {
                uint32_t bh[4];
                uint32_t addr = sb + b_lane_off + ng * (16 * ROWB) + kofs;
                ldsm4(bh[0], bh[1], bh[2], bh[3], addr);
#pragma unroll
                for (int mt = 0; mt < 4; mt++) {
#pragma unroll
                    for (int half = 0; half < 2; half++) {
                        float* a4 = acc[mt][ng * 2 + half];
                        mma16816(a4, ah[mt][0], ah[mt][1], ah[mt][2], ah[mt][3],
                                 bh[half*2], bh[half*2+1]);
                    }
                }
            }
        }
        buf = (buf + 1) % NSTAGE;
    }

    // Epilogue: direct fp32 stores
    const int rrow = lane >> 2;
    const int rcol = (lane & 3) * 2;
#pragma unroll
    for (int mt = 0; mt < 4; mt++) {
        const int row0 = bm + wm + mt * 16 + rrow;
#pragma unroll
        for (int nt = 0; nt < 8; nt++) {
            const int col = bn + wn + nt * 8 + rcol;
            *(float2*)(C + (size_t)row0 * N + col)       = make_float2(acc[mt][nt][0], acc[mt][nt][1]);
            *(float2*)(C + (size_t)(row0 + 8) * N + col) = make_float2(acc[mt][nt][2], acc[mt][nt][3]);
        }
    }
}

// ---------------------------------------------------------------------------
// Conv + gates (R11 version), channel-major outputs  [C, S]
// grid: (2048/32, 4096/32, BSZ), block: (32, 8)
// ---------------------------------------------------------------------------
__global__ __launch_bounds__(256)
void conv_gate_kernel(const float* __restrict__ cw)
{
    __shared__ float s_a[32][33];
    __shared__ float s_b[32][33];

    const int c  = blockIdx.x * 32 + threadIdx.x;
    const int fc = ((c >> 7) << 8) | (c & 127);
    const int ic = fc + 128;
    const int b  = blockIdx.z;
    const int t0 = blockIdx.y * 32;

    float wf[4], wi[4];
#pragma unroll
    for (int k = 0; k < 4; k++) { wf[k] = cw[fc * 4 + k]; wi[k] = cw[ic * 4 + k]; }

#pragma unroll
    for (int it = 0; it < 4; ++it) {
        const int tl = threadIdx.y + it * 8;
        const int t  = t0 + tl;
        const size_t rowbase = ((size_t)(b * SEQ + t)) * FOURH;
        float accf = 0.f, acci = 0.f;
#pragma unroll
        for (int k = 0; k < 4; k++) {
            int tp = t - 3 + k;
            if (tp >= 0) {
                size_t rb2 = ((size_t)(b * SEQ + tp)) * FOURH;
                accf = fmaf(wf[k], g_y[rb2 + 4096 + fc], accf);
                acci = fmaf(wi[k], g_y[rb2 + 4096 + ic], acci);
            }
        }
        const float h = g_y[rowbase + 2048 + c];
        const float f = 1.f / (1.f + __expf(-accf));
        const float i = 1.f / (1.f + __expf(-acci));
        const float denom = 1.f / (f + i + 1e-4f);
        s_a[tl][threadIdx.x] = f * denom;
        s_b[tl][threadIdx.x] = h * i * denom;
    }
    __syncthreads();

    const int lin = threadIdx.y * 32 + threadIdx.x;
    const int tw  = lin & 31;
    const int cb  = lin >> 5;
#pragma unroll
    for (int j = 0; j < 4; j++) {
        const int cl = cb + j * 8;
        const size_t idx = ((size_t)(b * HID + blockIdx.x * 32 + cl)) * SEQ + t0 + tw;
        g_a[idx] = s_a[tw][cl];
        g_b[idx] = s_b[tw][cl];
    }
}

// ---------------------------------------------------------------------------
// Linear scan per channel; warp-shuffle block scan (3 barriers)
// ---------------------------------------------------------------------------
__global__ __launch_bounds__(128)
void scan_kernel()
{
    const int ch  = blockIdx.x;
    const int tid = threadIdx.x;
    const int lane = tid & 31;
    const int wrp  = tid >> 5;
    const size_t base = (size_t)ch * SEQ + (size_t)tid * 32;

    float a[32], bb[32];
#pragma unroll
    for (int j = 0; j < 32; j += 4) {
        float4 va = *(const float4*)(g_a + base + j);
        float4 vb = *(const float4*)(g_b + base + j);
        a[j+0]=va.x; a[j+1]=va.y; a[j+2]=va.z; a[j+3]=va.w;
        bb[j+0]=vb.x; bb[j+1]=vb.y; bb[j+2]=vb.z; bb[j+3]=vb.w;
    }

    // chunk -> affine (A, B)
    float A = 1.f, Bv = 0.f;
#pragma unroll
    for (int j = 0; j < 32; j++) { Bv = fmaf(a[j], Bv, bb[j]); A *= a[j]; }

    // inclusive warp scan of affine pairs via shuffle
    float sAcc = A, sB = Bv;
#pragma unroll
    for (int off = 1; off < 32; off <<= 1) {
        float pA = __shfl_up_sync(0xFFFFFFFFu, sAcc, off);
        float pB = __shfl_up_sync(0xFFFFFFFFu, sB, off);
        if (lane >= off) { sB = fmaf(sAcc, pB, sB); sAcc *= pA; }
    }

    // cross-warp: warp totals scanned by warp 0
    __shared__ float wA[4], wB[4];
    if (lane == 31) { wA[wrp] = sAcc; wB[wrp] = sB; }
    __syncthreads();
    if (tid == 0) {
        float cA = wA[0], cB = wB[0];
#pragma unroll
        for (int w = 1; w < 4; w++) {
            cB = fmaf(wA[w], cB, wB[w]);
            cA *= wA[w];
            wA[w] = cA; wB[w] = cB;   // inclusive totals
        }
    }
    __syncthreads();

    // exclusive prefix for this thread = (prev warp inclusive) composed with (lane-1 inclusive)
    float preB;                 // h entering this thread's chunk
    {
        float warpPrevB = (wrp == 0) ? 0.f : wB[wrp - 1];
        // lane-exclusive within warp: value of lane-1's inclusive scan
        float lA = __shfl_up_sync(0xFFFFFFFFu, sAcc, 1);
        float lB = __shfl_up_sync(0xFFFFFFFFu, sB, 1);
        if (lane == 0) { lA = 1.f; lB = 0.f; }
        // h_in = lB + lA * warpPrevB  (apply warp-prefix through lane-prefix affine)
        preB = fmaf(lA, warpPrevB, lB);
    }

    float h = preB;
#pragma unroll
    for (int j = 0; j < 32; j++) { h = fmaf(a[j], h, bb[j]); bb[j] = h; }
#pragma unroll
    for (int j = 0; j < 32; j += 4)
        *(float4*)(g_hs + base + j) = make_float4(bb[j], bb[j+1], bb[j+2], bb[j+3]);
}

// ---------------------------------------------------------------------------
// g = silu(out1) * out2 ; writes fp16 for GEMM2
// ---------------------------------------------------------------------------
__global__ __launch_bounds__(256)
void silu_mul_kernel()
{
    __shared__ float sm[32][33];
    const int c0 = blockIdx.x * 32;
    const int s0 = blockIdx.y * 32;
    const int b  = blockIdx.z;

#pragma unroll
    for (int it = 0; it < 4; ++it) {
        const int cl = threadIdx.y + it * 8;
        const int s  = s0 + threadIdx.x;
        sm[cl][threadIdx.x] = g_hs[((size_t)(b * HID + c0 + cl)) * SEQ + s];
    }
    __syncthreads();

#pragma unroll
    for (int it = 0; it < 4; ++it) {
        const int sl = threadIdx.y + it * 8;
        const int s  = s0 + sl;
        const int c  = c0 + threadIdx.x;
        const size_t row = (size_t)(b * SEQ + s);
        const float o1 = g_y[row * FOURH + c];
        const float sil = o1 / (1.f + __expf(-o1));
        const float v = sil * sm[threadIdx.x][sl];
        g_gh[row * HID + c] = __float2half_rn(v);
    }
}

// ---------------------------------------------------------------------------
// Launch
// ---------------------------------------------------------------------------
extern "C" void kernel_launch(void* const* d_in, const int* in_sizes, int n_in,
                              void* d_out, int out_size)
{
    const float* x  = (const float*)d_in[0];
    const float* w1 = (const float*)d_in[1];
    const float* w2 = (const float*)d_in[2];
    const float* cw = (const float*)d_in[3];
    float* out = (float*)d_out;

    float *yp;
    cudaGetSymbolAddress((void**)&yp, g_y);
    __half *xh, *w1h, *w2h, *gh;
    cudaGetSymbolAddress((void**)&xh,  g_xh);
    cudaGetSymbolAddress((void**)&w1h, g_w1h);
    cudaGetSymbolAddress((void**)&w2h, g_w2h);
    cudaGetSymbolAddress((void**)&gh,  g_gh);

    cudaFuncSetAttribute(gemm_hmma_kernel, cudaFuncAttributeMaxDynamicSharedMemorySize, SMEMG);

    // fused conversions
    {
        const int nx4 = MROWS * EMB / 4;
        const int n14 = FOURH * EMB / 4;
        const int n24 = EMB * HID / 4;
        const int tot = nx4 + n14 + n24;
        round_all_kernel<<<(tot + 255) / 256, 256>>>(x, xh, nx4, w1, w1h, n14, w2, w2h, n24);
    }

    // GEMM1: y[M,8192] = x @ w1^T
    gemm_hmma_kernel<<<dim3(FOURH / BN, MROWS / BM), GTHREADS, SMEMG>>>(
        xh, w1h, yp, FOURH, EMB);

    conv_gate_kernel<<<dim3(HID / 32, SEQ / 32, BSZ), dim3(32, 8)>>>(cw);
    scan_kernel<<<NCH, 128>>>();
    silu_mul_kernel<<<dim3(HID / 32, SEQ / 32, BSZ), dim3(32, 8)>>>();

    // GEMM2: out[M,1024] = g @ w2^T
    gemm_hmma_kernel<<<dim3(EMB / BN, MROWS / BM), GTHREADS, SMEMG>>>(
        gh, w2h, out, EMB, HID);
}

// round 15
// speedup vs baseline: 1.2121x; 1.0571x over previous
#include <cuda_runtime.h>
#include <cuda_fp16.h>
#include <cstdint>

// ---------------------------------------------------------------------------
// Problem constants
// ---------------------------------------------------------------------------
#define BSZ      4
#define SEQ      4096
#define EMB      1024
#define HID      2048
#define FOURH    8192
#define MROWS    (BSZ*SEQ)      // 16384
#define NCH      (BSZ*HID)      // 8192 scan channels

// GEMM tile config (HMMA mma.sync — tcgen05 unavailable at .target sm_103)
#define BM 128
#define BN 128
#define BKK 64
#define ROWB 144                        // 128B data + 16B pad
#define A_MAT (128*ROWB)                // 18432
#define STAGE (2*A_MAT)                 // 36864
#define NSTAGE 3
#define SMEMG (NSTAGE*STAGE)            // 110592/CTA, 2 CTAs/SM
#define GTHREADS 128

// ---------------------------------------------------------------------------
// Scratch (static device globals)
// ---------------------------------------------------------------------------
__device__ float  g_y  [(size_t)MROWS * FOURH];
__device__ __half g_ah [(size_t)NCH   * SEQ];   // scan a, fp16 [C,S]
__device__ __half g_bh [(size_t)NCH   * SEQ];   // scan b, fp16 [C,S]
__device__ __half g_hsh[(size_t)NCH   * SEQ];   // scan out, fp16 [C,S]
__device__ __half g_xh [(size_t)MROWS * EMB];
__device__ __half g_w1h[(size_t)FOURH * EMB];
__device__ __half g_w2h[(size_t)EMB * HID];
__device__ __half g_gh [(size_t)MROWS * HID];

// ---------------------------------------------------------------------------
// PTX helpers (sm_80-baseline)
// ---------------------------------------------------------------------------
__device__ __forceinline__ uint32_t smem_u32(const void* p) {
    uint32_t a;
    asm("{ .reg .u64 t; cvta.to.shared.u64 t, %1; cvt.u32.u64 %0, t; }" : "=r"(a) : "l"(p));
    return a;
}
__device__ __forceinline__ void cp16(uint32_t s, const void* g) {
    asm volatile("cp.async.cg.shared.global [%0], [%1], 16;" :: "r"(s), "l"(g));
}
#define CP_COMMIT() asm volatile("cp.async.commit_group;" ::: "memory")
#define CP_WAIT(n)  asm volatile("cp.async.wait_group %0;" :: "n"(n) : "memory")

__device__ __forceinline__ void ldsm4(uint32_t& r0, uint32_t& r1, uint32_t& r2, uint32_t& r3,
                                      uint32_t addr) {
    asm volatile("ldmatrix.sync.aligned.m8n8.x4.shared.b16 {%0,%1,%2,%3}, [%4];"
                 : "=r"(r0), "=r"(r1), "=r"(r2), "=r"(r3) : "r"(addr));
}
__device__ __forceinline__ void mma16816(float* c, uint32_t a0, uint32_t a1, uint32_t a2,
                                         uint32_t a3, uint32_t b0, uint32_t b1) {
    asm volatile(
        "mma.sync.aligned.m16n8k16.row.col.f32.f16.f16.f32 "
        "{%0,%1,%2,%3}, {%4,%5,%6,%7}, {%8,%9}, {%0,%1,%2,%3};"
        : "+f"(c[0]), "+f"(c[1]), "+f"(c[2]), "+f"(c[3])
        : "r"(a0), "r"(a1), "r"(a2), "r"(a3), "r"(b0), "r"(b1));
}

// ---------------------------------------------------------------------------
// Fused fp32 -> fp16 round over x | w1 | w2
// ---------------------------------------------------------------------------
__global__ __launch_bounds__(256)
void round_all_kernel(const float* __restrict__ x,  __half* __restrict__ xh,  int nx4,
                      const float* __restrict__ w1, __half* __restrict__ w1h, int n14,
                      const float* __restrict__ w2, __half* __restrict__ w2h, int n24)
{
    int i = blockIdx.x * 256 + threadIdx.x;
    const float* in; __half* out; int idx;
    if (i < nx4) { in = x; out = xh; idx = i; }
    else if (i < nx4 + n14) { in = w1; out = w1h; idx = i - nx4; }
    else if (i < nx4 + n14 + n24) { in = w2; out = w2h; idx = i - nx4 - n14; }
    else return;
    float4 v = ((const float4*)in)[idx];
    __half2* op = (__half2*)out;
    op[2*idx]   = __half2(__float2half_rn(v.x), __float2half_rn(v.y));
    op[2*idx+1] = __half2(__float2half_rn(v.z), __float2half_rn(v.w));
}

// ---------------------------------------------------------------------------
// HMMA fp16 GEMM (exact R11/R14 version — best measured)
// ---------------------------------------------------------------------------
__global__ __launch_bounds__(GTHREADS, 2)
void gemm_hmma_kernel(const __half* __restrict__ Ah,
                      const __half* __restrict__ Bh,
                      float* __restrict__ C, int N, int K)
{
    extern __shared__ char smem[];
    const uint32_t sbase = smem_u32(smem);
    const int tid  = threadIdx.x;
    const int wid  = tid >> 5;
    const int lane = tid & 31;
    const int bm = blockIdx.y * BM;
    const int bn = blockIdx.x * BN;
    const int wm = (wid >> 1) * 64;
    const int wn = (wid & 1) * 64;

    const int NC = K / BKK;

    const int lrow = tid >> 3;
    const int lch  = tid & 7;
    auto load_stage = [&](int kc, int buf) {
        const uint32_t sb = sbase + buf * STAGE;
        const int k0 = kc * BKK;
#pragma unroll
        for (int j = 0; j < 8; j++) {
            int r = lrow + j * 16;
            size_t goA = (size_t)(bm + r) * K + k0 + lch * 8;
            size_t goB = (size_t)(bn + r) * K + k0 + lch * 8;
            uint32_t so = sb + r * ROWB + lch * 16;
            cp16(so,         Ah + goA);
            cp16(so + A_MAT, Bh + goB);
        }
    };

    const int lr  = lane & 7;
    const int sel = lane >> 3;
    const uint32_t a_lane_off = (uint32_t)((wm + lr + ((sel & 1) << 3)) * ROWB + ((sel >> 1) << 4));
    const uint32_t b_lane_off = (uint32_t)(A_MAT + (wn + lr + ((sel >> 1) << 3)) * ROWB + ((sel & 1) << 4));

    float acc[4][8][4];
#pragma unroll
    for (int mt = 0; mt < 4; mt++)
#pragma unroll
        for (int nt = 0; nt < 8; nt++)
#pragma unroll
            for (int r = 0; r < 4; r++) acc[mt][nt][r] = 0.f;

    load_stage(0, 0); CP_COMMIT();
    load_stage(1, 1); CP_COMMIT();

    int buf = 0;
    for (int it = 0; it < NC; it++) {
        if (it + 1 < NC) { CP_WAIT(1); } else { CP_WAIT(0); }
        __syncthreads();

        if (it + 2 < NC) { load_stage(it + 2, (buf + 2) % NSTAGE); CP_COMMIT(); }

        const uint32_t sb = sbase + buf * STAGE;
#pragma unroll
        for (int ks = 0; ks < 4; ks++) {
            const uint32_t kofs = ks * 32;
            uint32_t ah[4][4];
#pragma unroll
            for (int mt = 0; mt < 4; mt++) {
                uint32_t addr = sb + a_lane_off + mt * (16 * ROWB) + kofs;
                ldsm4(ah[mt][0], ah[mt][1], ah[mt][2], ah[mt][3], addr);
            }
#pragma unroll
            for (int ng = 0; ng < 4; ng++) {
                uint32_t bh[4];
                uint32_t addr = sb + b_lane_off + ng * (16 * ROWB) + kofs;
                ldsm4(bh[0], bh[1], bh[2], bh[3], addr);
#pragma unroll
                for (int mt = 0; mt < 4; mt++) {
#pragma unroll
                    for (int half = 0; half < 2; half++) {
                        float* a4 = acc[mt][ng * 2 + half];
                        mma16816(a4, ah[mt][0], ah[mt][1], ah[mt][2], ah[mt][3],
                                 bh[half*2], bh[half*2+1]);
                    }
                }
            }
        }
        buf = (buf + 1) % NSTAGE;
    }

    const int rrow = lane >> 2;
    const int rcol = (lane & 3) * 2;
#pragma unroll
    for (int mt = 0; mt < 4; mt++) {
        const int row0 = bm + wm + mt * 16 + rrow;
#pragma unroll
        for (int nt = 0; nt < 8; nt++) {
            const int col = bn + wn + nt * 8 + rcol;
            *(float2*)(C + (size_t)row0 * N + col)       = make_float2(acc[mt][nt][0], acc[mt][nt][1]);
            *(float2*)(C + (size_t)(row0 + 8) * N + col) = make_float2(acc[mt][nt][2], acc[mt][nt][3]);
        }
    }
}

// ---------------------------------------------------------------------------
// Conv + gates, fp16 channel-major outputs  [C, S]
// ---------------------------------------------------------------------------
__global__ __launch_bounds__(256)
void conv_gate_kernel(const float* __restrict__ cw)
{
    __shared__ float s_a[32][33];
    __shared__ float s_b[32][33];

    const int c  = blockIdx.x * 32 + threadIdx.x;
    const int fc = ((c >> 7) << 8) | (c & 127);
    const int ic = fc + 128;
    const int b  = blockIdx.z;
    const int t0 = blockIdx.y * 32;

    float wf[4], wi[4];
#pragma unroll
    for (int k = 0; k < 4; k++) { wf[k] = cw[fc * 4 + k]; wi[k] = cw[ic * 4 + k]; }

#pragma unroll
    for (int it = 0; it < 4; ++it) {
        const int tl = threadIdx.y + it * 8;
        const int t  = t0 + tl;
        const size_t rowbase = ((size_t)(b * SEQ + t)) * FOURH;
        float accf = 0.f, acci = 0.f;
#pragma unroll
        for (int k = 0; k < 4; k++) {
            int tp = t - 3 + k;
            if (tp >= 0) {
                size_t rb2 = ((size_t)(b * SEQ + tp)) * FOURH;
                accf = fmaf(wf[k], g_y[rb2 + 4096 + fc], accf);
                acci = fmaf(wi[k], g_y[rb2 + 4096 + ic], acci);
            }
        }
        const float h = g_y[rowbase + 2048 + c];
        const float f = 1.f / (1.f + __expf(-accf));
        const float i = 1.f / (1.f + __expf(-acci));
        const float denom = 1.f / (f + i + 1e-4f);
        s_a[tl][threadIdx.x] = f * denom;
        s_b[tl][threadIdx.x] = h * i * denom;
    }
    __syncthreads();

    const int lin = threadIdx.y * 32 + threadIdx.x;
    const int tw  = lin & 31;
    const int cb  = lin >> 5;
#pragma unroll
    for (int j = 0; j < 4; j++) {
        const int cl = cb + j * 8;
        const size_t idx = ((size_t)(b * HID + blockIdx.x * 32 + cl)) * SEQ + t0 + tw;
        g_ah[idx] = __float2half_rn(s_a[tw][cl]);
        g_bh[idx] = __float2half_rn(s_b[tw][cl]);
    }
}

// ---------------------------------------------------------------------------
// Linear scan per channel; fp16 in/out, fp32 math; warp-shuffle block scan
// ---------------------------------------------------------------------------
__global__ __launch_bounds__(128)
void scan_kernel()
{
    const int ch  = blockIdx.x;
    const int tid = threadIdx.x;
    const int lane = tid & 31;
    const int wrp  = tid >> 5;
    const size_t base = (size_t)ch * SEQ + (size_t)tid * 32;

    float a[32], bb[32];
#pragma unroll
    for (int j = 0; j < 4; j++) {           // 4 x uint4 = 32 halfs
        uint4 ua = *(const uint4*)(g_ah + base + j * 8);
        uint4 ub = *(const uint4*)(g_bh + base + j * 8);
        const uint32_t* wa = (const uint32_t*)&ua;
        const uint32_t* wb = (const uint32_t*)&ub;
#pragma unroll
        for (int q = 0; q < 4; q++) {
            float2 va = __half22float2(*(const __half2*)&wa[q]);
            float2 vb = __half22float2(*(const __half2*)&wb[q]);
            a [j*8 + q*2 + 0] = va.x; a [j*8 + q*2 + 1] = va.y;
            bb[j*8 + q*2 + 0] = vb.x; bb[j*8 + q*2 + 1] = vb.y;
        }
    }

    // chunk -> affine (A, B)
    float A = 1.f, Bv = 0.f;
#pragma unroll
    for (int j = 0; j < 32; j++) { Bv = fmaf(a[j], Bv, bb[j]); A *= a[j]; }

    // inclusive warp scan via shuffle
    float sAcc = A, sB = Bv;
#pragma unroll
    for (int off = 1; off < 32; off <<= 1) {
        float pA = __shfl_up_sync(0xFFFFFFFFu, sAcc, off);
        float pB = __shfl_up_sync(0xFFFFFFFFu, sB, off);
        if (lane >= off) { sB = fmaf(sAcc, pB, sB); sAcc *= pA; }
    }

    __shared__ float wA[4], wB[4];
    if (lane == 31) { wA[wrp] = sAcc; wB[wrp] = sB; }
    __syncthreads();
    if (tid == 0) {
        float cA = wA[0], cB = wB[0];
#pragma unroll
        for (int w = 1; w < 4; w++) {
            cB = fmaf(wA[w], cB, wB[w]);
            cA *= wA[w];
            wA[w] = cA; wB[w] = cB;
        }
    }
    __syncthreads();

    float preB;
    {
        float warpPrevB = (wrp == 0) ? 0.f : wB[wrp - 1];
        float lA = __shfl_up_sync(0xFFFFFFFFu, sAcc, 1);
        float lB = __shfl_up_sync(0xFFFFFFFFu, sB, 1);
        if (lane == 0) { lA = 1.f; lB = 0.f; }
        preB = fmaf(lA, warpPrevB, lB);
    }

    float h = preB;
    __half hout[32];
#pragma unroll
    for (int j = 0; j < 32; j++) { h = fmaf(a[j], h, bb[j]); hout[j] = __float2half_rn(h); }
#pragma unroll
    for (int j = 0; j < 4; j++)
        *(uint4*)(g_hsh + base + j * 8) = *(const uint4*)&hout[j * 8];
}

// ---------------------------------------------------------------------------
// g = silu(out1) * out2 ; reads fp16 hs, writes fp16 g
// ---------------------------------------------------------------------------
__global__ __launch_bounds__(256)
void silu_mul_kernel()
{
    __shared__ float sm[32][33];
    const int c0 = blockIdx.x * 32;
    const int s0 = blockIdx.y * 32;
    const int b  = blockIdx.z;

#pragma unroll
    for (int it = 0; it < 4; ++it) {
        const int cl = threadIdx.y + it * 8;
        const int s  = s0 + threadIdx.x;
        sm[cl][threadIdx.x] = __half2float(g_hsh[((size_t)(b * HID + c0 + cl)) * SEQ + s]);
    }
    __syncthreads();

#pragma unroll
    for (int it = 0; it < 4; ++it) {
        const int sl = threadIdx.y + it * 8;
        const int s  = s0 + sl;
        const int c  = c0 + threadIdx.x;
        const size_t row = (size_t)(b * SEQ + s);
        const float o1 = g_y[row * FOURH + c];
        const float sil = o1 / (1.f + __expf(-o1));
        const float v = sil * sm[threadIdx.x][sl];
        g_gh[row * HID + c] = __float2half_rn(v);
    }
}

// ---------------------------------------------------------------------------
// Launch
// ---------------------------------------------------------------------------
extern "C" void kernel_launch(void* const* d_in, const int* in_sizes, int n_in,
                              void* d_out, int out_size)
{
    const float* x  = (const float*)d_in[0];
    const float* w1 = (const float*)d_in[1];
    const float* w2 = (const float*)d_in[2];
    const float* cw = (const float*)d_in[3];
    float* out = (float*)d_out;

    float *yp;
    cudaGetSymbolAddress((void**)&yp, g_y);
    __half *xh, *w1h, *w2h, *gh;
    cudaGetSymbolAddress((void**)&xh,  g_xh);
    cudaGetSymbolAddress((void**)&w1h, g_w1h);
    cudaGetSymbolAddress((void**)&w2h, g_w2h);
    cudaGetSymbolAddress((void**)&gh,  g_gh);

    cudaFuncSetAttribute(gemm_hmma_kernel, cudaFuncAttributeMaxDynamicSharedMemorySize, SMEMG);

    // fused conversions
    {
        const int nx4 = MROWS * EMB / 4;
        const int n14 = FOURH * EMB / 4;
        const int n24 = EMB * HID / 4;
        const int tot = nx4 + n14 + n24;
        round_all_kernel<<<(tot + 255) / 256, 256>>>(x, xh, nx4, w1, w1h, n14, w2, w2h, n24);
    }

    // GEMM1: y[M,8192] = x @ w1^T
    gemm_hmma_kernel<<<dim3(FOURH / BN, MROWS / BM), GTHREADS, SMEMG>>>(
        xh, w1h, yp, FOURH, EMB);

    conv_gate_kernel<<<dim3(HID / 32, SEQ / 32, BSZ), dim3(32, 8)>>>(cw);
    scan_kernel<<<NCH, 128>>>();
    silu_mul_kernel<<<dim3(HID / 32, SEQ / 32, BSZ), dim3(32, 8)>>>();

    // GEMM2: out[M,1024] = g @ w2^T
    gemm_hmma_kernel<<<dim3(EMB / BN, MROWS / BM), GTHREADS, SMEMG>>>(
        gh, w2h, out, EMB, HID);
}

// round 16
// speedup vs baseline: 1.2499x; 1.0312x over previous
#include <cuda_runtime.h>
#include <cuda_fp16.h>
#include <cstdint>

// ---------------------------------------------------------------------------
// Problem constants
// ---------------------------------------------------------------------------
#define BSZ      4
#define SEQ      4096
#define EMB      1024
#define HID      2048
#define FOURH    8192
#define MROWS    (BSZ*SEQ)      // 16384
#define NCH      (BSZ*HID)      // 8192 scan channels

// GEMM tile config (HMMA mma.sync — tcgen05 unavailable at .target sm_103)
#define BM 128
#define BN 128
#define BKK 64
#define ROWB 144                        // 128B data + 16B pad
#define A_MAT (128*ROWB)                // 18432
#define STAGE (2*A_MAT)                 // 36864
#define NSTAGE 3
#define SMEMG (NSTAGE*STAGE)            // 110592/CTA, 2 CTAs/SM
#define GTHREADS 128

// ---------------------------------------------------------------------------
// Scratch (static device globals)
// ---------------------------------------------------------------------------
__device__ float  g_y  [(size_t)MROWS * FOURH];
__device__ __half g_ah [(size_t)NCH   * SEQ];
__device__ __half g_bh [(size_t)NCH   * SEQ];
__device__ __half g_hsh[(size_t)NCH   * SEQ];
__device__ __half g_xh [(size_t)MROWS * EMB];
__device__ __half g_w1h[(size_t)FOURH * EMB];
__device__ __half g_w2h[(size_t)EMB * HID];
__device__ __half g_gh [(size_t)MROWS * HID];

// ---------------------------------------------------------------------------
// PTX helpers (sm_80-baseline)
// ---------------------------------------------------------------------------
__device__ __forceinline__ uint32_t smem_u32(const void* p) {
    uint32_t a;
    asm("{ .reg .u64 t; cvta.to.shared.u64 t, %1; cvt.u32.u64 %0, t; }" : "=r"(a) : "l"(p));
    return a;
}
__device__ __forceinline__ void cp16(uint32_t s, const void* g) {
    asm volatile("cp.async.cg.shared.global [%0], [%1], 16;" :: "r"(s), "l"(g));
}
#define CP_COMMIT() asm volatile("cp.async.commit_group;" ::: "memory")
#define CP_WAIT(n)  asm volatile("cp.async.wait_group %0;" :: "n"(n) : "memory")

__device__ __forceinline__ void ldsm4(uint32_t& r0, uint32_t& r1, uint32_t& r2, uint32_t& r3,
                                      uint32_t addr) {
    asm volatile("ldmatrix.sync.aligned.m8n8.x4.shared.b16 {%0,%1,%2,%3}, [%4];"
                 : "=r"(r0), "=r"(r1), "=r"(r2), "=r"(r3) : "r"(addr));
}
__device__ __forceinline__ void mma16816(float* c, uint32_t a0, uint32_t a1, uint32_t a2,
                                         uint32_t a3, uint32_t b0, uint32_t b1) {
    asm volatile(
        "mma.sync.aligned.m16n8k16.row.col.f32.f16.f16.f32 "
        "{%0,%1,%2,%3}, {%4,%5,%6,%7}, {%8,%9}, {%0,%1,%2,%3};"
        : "+f"(c[0]), "+f"(c[1]), "+f"(c[2]), "+f"(c[3])
        : "r"(a0), "r"(a1), "r"(a2), "r"(a3), "r"(b0), "r"(b1));
}

// ---------------------------------------------------------------------------
// Fused fp32 -> fp16 round over x | w1 | w2
// ---------------------------------------------------------------------------
__global__ __launch_bounds__(256)
void round_all_kernel(const float* __restrict__ x,  __half* __restrict__ xh,  int nx4,
                      const float* __restrict__ w1, __half* __restrict__ w1h, int n14,
                      const float* __restrict__ w2, __half* __restrict__ w2h, int n24)
{
    int i = blockIdx.x * 256 + threadIdx.x;
    const float* in; __half* out; int idx;
    if (i < nx4) { in = x; out = xh; idx = i; }
    else if (i < nx4 + n14) { in = w1; out = w1h; idx = i - nx4; }
    else if (i < nx4 + n14 + n24) { in = w2; out = w2h; idx = i - nx4 - n14; }
    else return;
    float4 v = ((const float4*)in)[idx];
    __half2* op = (__half2*)out;
    op[2*idx]   = __half2(__float2half_rn(v.x), __float2half_rn(v.y));
    op[2*idx+1] = __half2(__float2half_rn(v.z), __float2half_rn(v.w));
}

// ---------------------------------------------------------------------------
// HMMA fp16 GEMM (exact R11/R14 version — best measured)
// ---------------------------------------------------------------------------
__global__ __launch_bounds__(GTHREADS, 2)
void gemm_hmma_kernel(const __half* __restrict__ Ah,
                      const __half* __restrict__ Bh,
                      float* __restrict__ C, int N, int K)
{
    extern __shared__ char smem[];
    const uint32_t sbase = smem_u32(smem);
    const int tid  = threadIdx.x;
    const int wid  = tid >> 5;
    const int lane = tid & 31;
    const int bm = blockIdx.y * BM;
    const int bn = blockIdx.x * BN;
    const int wm = (wid >> 1) * 64;
    const int wn = (wid & 1) * 64;

    const int NC = K / BKK;

    const int lrow = tid >> 3;
    const int lch  = tid & 7;
    auto load_stage = [&](int kc, int buf) {
        const uint32_t sb = sbase + buf * STAGE;
        const int k0 = kc * BKK;
#pragma unroll
        for (int j = 0; j < 8; j++) {
            int r = lrow + j * 16;
            size_t goA = (size_t)(bm + r) * K + k0 + lch * 8;
            size_t goB = (size_t)(bn + r) * K + k0 + lch * 8;
            uint32_t so = sb + r * ROWB + lch * 16;
            cp16(so,         Ah + goA);
            cp16(so + A_MAT, Bh + goB);
        }
    };

    const int lr  = lane & 7;
    const int sel = lane >> 3;
    const uint32_t a_lane_off = (uint32_t)((wm + lr + ((sel & 1) << 3)) * ROWB + ((sel >> 1) << 4));
    const uint32_t b_lane_off = (uint32_t)(A_MAT + (wn + lr + ((sel >> 1) << 3)) * ROWB + ((sel & 1) << 4));

    float acc[4][8][4];
#pragma unroll
    for (int mt = 0; mt < 4; mt++)
#pragma unroll
        for (int nt = 0; nt < 8; nt++)
#pragma unroll
            for (int r = 0; r < 4; r++) acc[mt][nt][r] = 0.f;

    load_stage(0, 0); CP_COMMIT();
    load_stage(1, 1); CP_COMMIT();

    int buf = 0;
    for (int it = 0; it < NC; it++) {
        if (it + 1 < NC) { CP_WAIT(1); } else { CP_WAIT(0); }
        __syncthreads();

        if (it + 2 < NC) { load_stage(it + 2, (buf + 2) % NSTAGE); CP_COMMIT(); }

        const uint32_t sb = sbase + buf * STAGE;
#pragma unroll
        for (int ks = 0; ks < 4; ks++) {
            const uint32_t kofs = ks * 32;
            uint32_t ah[4][4];
#pragma unroll
            for (int mt = 0; mt < 4; mt++) {
                uint32_t addr = sb + a_lane_off + mt * (16 * ROWB) + kofs;
                ldsm4(ah[mt][0], ah[mt][1], ah[mt][2], ah[mt][3], addr);
            }
#pragma unroll
            for (int ng = 0; ng < 4; ng++) {
                uint32_t bh[4];
                uint32_t addr = sb + b_lane_off + ng * (16 * ROWB) + kofs;
                ldsm4(bh[0], bh[1], bh[2], bh[3], addr);
#pragma unroll
                for (int mt = 0; mt < 4; mt++) {
#pragma unroll
                    for (int half = 0; half < 2; half++) {
                        float* a4 = acc[mt][ng * 2 + half];
                        mma16816(a4, ah[mt][0], ah[mt][1], ah[mt][2], ah[mt][3],
                                 bh[half*2], bh[half*2+1]);
                    }
                }
            }
        }
        buf = (buf + 1) % NSTAGE;
    }

    const int rrow = lane >> 2;
    const int rcol = (lane & 3) * 2;
#pragma unroll
    for (int mt = 0; mt < 4; mt++) {
        const int row0 = bm + wm + mt * 16 + rrow;
#pragma unroll
        for (int nt = 0; nt < 8; nt++) {
            const int col = bn + wn + nt * 8 + rcol;
            *(float2*)(C + (size_t)row0 * N + col)       = make_float2(acc[mt][nt][0], acc[mt][nt][1]);
            *(float2*)(C + (size_t)(row0 + 8) * N + col) = make_float2(acc[mt][nt][2], acc[mt][nt][3]);
        }
    }
}

// ---------------------------------------------------------------------------
// Conv + gates, rolling 4-t window per thread, coalesced across channels.
// block (32, 8): tx = channel within 32-tile, ty = 4-t chunk (t = t0+ty*4..+3).
// fp16 channel-major outputs [C, S] via smem transpose.
// ---------------------------------------------------------------------------
__global__ __launch_bounds__(256)
void conv_gate_kernel(const float* __restrict__ cw)
{
    __shared__ float s_a[32][33];
    __shared__ float s_b[32][33];

    const int c  = blockIdx.x * 32 + threadIdx.x;
    const int fc = ((c >> 7) << 8) | (c & 127);
    const int ic = fc + 128;
    const int b  = blockIdx.z;
    const int t0 = blockIdx.y * 32;
    const int tb = t0 + threadIdx.y * 4;       // first t of this thread's chunk

    float wf[4], wi[4];
#pragma unroll
    for (int k = 0; k < 4; k++) { wf[k] = cw[fc * 4 + k]; wi[k] = cw[ic * 4 + k]; }

    const float* yf = g_y + (size_t)(b * SEQ) * FOURH + 4096 + fc;
    const float* yi = g_y + (size_t)(b * SEQ) * FOURH + 4096 + ic;
    const float* yh = g_y + (size_t)(b * SEQ) * FOURH + 2048 + c;

    // rolling history f/i at t-3, t-2, t-1
    float f0, f1, f2, i0, i1, i2;
    {
        int tp = tb - 3;
        f0 = (tp >= 0) ? yf[(size_t)tp * FOURH] : 0.f;
        i0 = (tp >= 0) ? yi[(size_t)tp * FOURH] : 0.f;
        tp = tb - 2;
        f1 = (tp >= 0) ? yf[(size_t)tp * FOURH] : 0.f;
        i1 = (tp >= 0) ? yi[(size_t)tp * FOURH] : 0.f;
        tp = tb - 1;
        f2 = (tp >= 0) ? yf[(size_t)tp * FOURH] : 0.f;
        i2 = (tp >= 0) ? yi[(size_t)tp * FOURH] : 0.f;
    }

#pragma unroll
    for (int j = 0; j < 4; j++) {
        const int t = tb + j;
        const float vf = yf[(size_t)t * FOURH];
        const float vi = yi[(size_t)t * FOURH];
        const float h  = yh[(size_t)t * FOURH];
        const float accf = wf[0]*f0 + wf[1]*f1 + wf[2]*f2 + wf[3]*vf;
        const float acci = wi[0]*i0 + wi[1]*i1 + wi[2]*i2 + wi[3]*vi;
        f0 = f1; f1 = f2; f2 = vf;
        i0 = i1; i1 = i2; i2 = vi;
        const float f = 1.f / (1.f + __expf(-accf));
        const float i = 1.f / (1.f + __expf(-acci));
        const float denom = 1.f / (f + i + 1e-4f);
        const int tl = threadIdx.y * 4 + j;     // t within 32-tile
        s_a[tl][threadIdx.x] = f * denom;
        s_b[tl][threadIdx.x] = h * i * denom;
    }
    __syncthreads();

    const int lin = threadIdx.y * 32 + threadIdx.x;
    const int tw  = lin & 31;
    const int cb  = lin >> 5;
#pragma unroll
    for (int j = 0; j < 4; j++) {
        const int cl = cb + j * 8;
        const size_t idx = ((size_t)(b * HID + blockIdx.x * 32 + cl)) * SEQ + t0 + tw;
        g_ah[idx] = __float2half_rn(s_a[tw][cl]);
        g_bh[idx] = __float2half_rn(s_b[tw][cl]);
    }
}

// ---------------------------------------------------------------------------
// Linear scan per channel; fp16 in/out, fp32 math; warp-shuffle block scan
// ---------------------------------------------------------------------------
__global__ __launch_bounds__(128)
void scan_kernel()
{
    const int ch  = blockIdx.x;
    const int tid = threadIdx.x;
    const int lane = tid & 31;
    const int wrp  = tid >> 5;
    const size_t base = (size_t)ch * SEQ + (size_t)tid * 32;

    float a[32], bb[32];
#pragma unroll
    for (int j = 0; j < 4; j++) {
        uint4 ua = *(const uint4*)(g_ah + base + j * 8);
        uint4 ub = *(const uint4*)(g_bh + base + j * 8);
        const uint32_t* wa = (const uint32_t*)&ua;
        const uint32_t* wb = (const uint32_t*)&ub;
#pragma unroll
        for (int q = 0; q < 4; q++) {
            float2 va = __half22float2(*(const __half2*)&wa[q]);
            float2 vb = __half22float2(*(const __half2*)&wb[q]);
            a [j*8 + q*2 + 0] = va.x; a [j*8 + q*2 + 1] = va.y;
            bb[j*8 + q*2 + 0] = vb.x; bb[j*8 + q*2 + 1] = vb.y;
        }
    }

    float A = 1.f, Bv = 0.f;
#pragma unroll
    for (int j = 0; j < 32; j++) { Bv = fmaf(a[j], Bv, bb[j]); A *= a[j]; }

    float sAcc = A, sB = Bv;
#pragma unroll
    for (int off = 1; off < 32; off <<= 1) {
        float pA = __shfl_up_sync(0xFFFFFFFFu, sAcc, off);
        float pB = __shfl_up_sync(0xFFFFFFFFu, sB, off);
        if (lane >= off) { sB = fmaf(sAcc, pB, sB); sAcc *= pA; }
    }

    __shared__ float wA[4], wB[4];
    if (lane == 31) { wA[wrp] = sAcc; wB[wrp] = sB; }
    __syncthreads();
    if (tid == 0) {
        float cA = wA[0], cB = wB[0];
#pragma unroll
        for (int w = 1; w < 4; w++) {
            cB = fmaf(wA[w], cB, wB[w]);
            cA *= wA[w];
            wA[w] = cA; wB[w] = cB;
        }
    }
    __syncthreads();

    float preB;
    {
        float warpPrevB = (wrp == 0) ? 0.f : wB[wrp - 1];
        float lA = __shfl_up_sync(0xFFFFFFFFu, sAcc, 1);
        float lB = __shfl_up_sync(0xFFFFFFFFu, sB, 1);
        if (lane == 0) { lA = 1.f; lB = 0.f; }
        preB = fmaf(lA, warpPrevB, lB);
    }

    float h = preB;
    __half hout[32];
#pragma unroll
    for (int j = 0; j < 32; j++) { h = fmaf(a[j], h, bb[j]); hout[j] = __float2half_rn(h); }
#pragma unroll
    for (int j = 0; j < 4; j++)
        *(uint4*)(g_hsh + base + j * 8) = *(const uint4*)&hout[j * 8];
}

// ---------------------------------------------------------------------------
// g = silu(out1) * out2 ; reads fp16 hs, writes fp16 g
// ---------------------------------------------------------------------------
__global__ __launch_bounds__(256)
void silu_mul_kernel()
{
    __shared__ float sm[32][33];
    const int c0 = blockIdx.x * 32;
    const int s0 = blockIdx.y * 32;
    const int b  = blockIdx.z;

#pragma unroll
    for (int it = 0; it < 4; ++it) {
        const int cl = threadIdx.y + it * 8;
        const int s  = s0 + threadIdx.x;
        sm[cl][threadIdx.x] = __half2float(g_hsh[((size_t)(b * HID + c0 + cl)) * SEQ + s]);
    }
    __syncthreads();

#pragma unroll
    for (int it = 0; it < 4; ++it) {
        const int sl = threadIdx.y + it * 8;
        const int s  = s0 + sl;
        const int c  = c0 + threadIdx.x;
        const size_t row = (size_t)(b * SEQ + s);
        const float o1 = g_y[row * FOURH + c];
        const float sil = o1 / (1.f + __expf(-o1));
        const float v = sil * sm[threadIdx.x][sl];
        g_gh[row * HID + c] = __float2half_rn(v);
    }
}

// ---------------------------------------------------------------------------
// Launch
// ---------------------------------------------------------------------------
extern "C" void kernel_launch(void* const* d_in, const int* in_sizes, int n_in,
                              void* d_out, int out_size)
{
    const float* x  = (const float*)d_in[0];
    const float* w1 = (const float*)d_in[1];
    const float* w2 = (const float*)d_in[2];
    const float* cw = (const float*)d_in[3];
    float* out = (float*)d_out;

    float *yp;
    cudaGetSymbolAddress((void**)&yp, g_y);
    __half *xh, *w1h, *w2h, *gh;
    cudaGetSymbolAddress((void**)&xh,  g_xh);
    cudaGetSymbolAddress((void**)&w1h, g_w1h);
    cudaGetSymbolAddress((void**)&w2h, g_w2h);
    cudaGetSymbolAddress((void**)&gh,  g_gh);

    cudaFuncSetAttribute(gemm_hmma_kernel, cudaFuncAttributeMaxDynamicSharedMemorySize, SMEMG);

    // fused conversions
    {
        const int nx4 = MROWS * EMB / 4;
        const int n14 = FOURH * EMB / 4;
        const int n24 = EMB * HID / 4;
        const int tot = nx4 + n14 + n24;
        round_all_kernel<<<(tot + 255) / 256, 256>>>(x, xh, nx4, w1, w1h, n14, w2, w2h, n24);
    }

    // GEMM1: y[M,8192] = x @ w1^T
    gemm_hmma_kernel<<<dim3(FOURH / BN, MROWS / BM), GTHREADS, SMEMG>>>(
        xh, w1h, yp, FOURH, EMB);

    conv_gate_kernel<<<dim3(HID / 32, SEQ / 32, BSZ), dim3(32, 8)>>>(cw);
    scan_kernel<<<NCH, 128>>>();
    silu_mul_kernel<<<dim3(HID / 32, SEQ / 32, BSZ), dim3(32, 8)>>>();

    // GEMM2: out[M,1024] = g @ w2^T
    gemm_hmma_kernel<<<dim3(EMB / BN, MROWS / BM), GTHREADS, SMEMG>>>(
        gh, w2h, out, EMB, HID);
}

// round 17
// speedup vs baseline: 1.2645x; 1.0117x over previous
#include <cuda_runtime.h>
#include <cuda_fp16.h>
#include <cstdint>

// ---------------------------------------------------------------------------
// Problem constants
// ---------------------------------------------------------------------------
#define BSZ      4
#define SEQ      4096
#define EMB      1024
#define HID      2048
#define FOURH    8192
#define MROWS    (BSZ*SEQ)      // 16384
#define NCH      (BSZ*HID)      // 8192 scan channels

// GEMM tile config (HMMA mma.sync — tcgen05 unavailable at .target sm_103)
#define BM 128
#define BN 128
#define BKK 64
#define ROWB 144                        // 128B data + 16B pad
#define A_MAT (128*ROWB)                // 18432
#define STAGE (2*A_MAT)                 // 36864
#define NSTAGE 3
#define SMEMG (NSTAGE*STAGE)            // 110592/CTA, 2 CTAs/SM
#define GTHREADS 128

// ---------------------------------------------------------------------------
// Scratch (static device globals)
// ---------------------------------------------------------------------------
__device__ float  g_y  [(size_t)MROWS * FOURH];
__device__ __half g_ah [(size_t)NCH   * SEQ];
__device__ __half g_bh [(size_t)NCH   * SEQ];
__device__ __half g_hsh[(size_t)NCH   * SEQ];
__device__ __half g_xh [(size_t)MROWS * EMB];
__device__ __half g_w1h[(size_t)FOURH * EMB];
__device__ __half g_w2h[(size_t)EMB * HID];
__device__ __half g_gh [(size_t)MROWS * HID];

// ---------------------------------------------------------------------------
// PTX helpers (sm_80-baseline)
// ---------------------------------------------------------------------------
__device__ __forceinline__ uint32_t smem_u32(const void* p) {
    uint32_t a;
    asm("{ .reg .u64 t; cvta.to.shared.u64 t, %1; cvt.u32.u64 %0, t; }" : "=r"(a) : "l"(p));
    return a;
}
__device__ __forceinline__ void cp16(uint32_t s, const void* g) {
    asm volatile("cp.async.cg.shared.global [%0], [%1], 16;" :: "r"(s), "l"(g));
}
#define CP_COMMIT() asm volatile("cp.async.commit_group;" ::: "memory")
#define CP_WAIT(n)  asm volatile("cp.async.wait_group %0;" :: "n"(n) : "memory")

__device__ __forceinline__ void ldsm4(uint32_t& r0, uint32_t& r1, uint32_t& r2, uint32_t& r3,
                                      uint32_t addr) {
    asm volatile("ldmatrix.sync.aligned.m8n8.x4.shared.b16 {%0,%1,%2,%3}, [%4];"
                 : "=r"(r0), "=r"(r1), "=r"(r2), "=r"(r3) : "r"(addr));
}
__device__ __forceinline__ void mma16816(float* c, uint32_t a0, uint32_t a1, uint32_t a2,
                                         uint32_t a3, uint32_t b0, uint32_t b1) {
    asm volatile(
        "mma.sync.aligned.m16n8k16.row.col.f32.f16.f16.f32 "
        "{%0,%1,%2,%3}, {%4,%5,%6,%7}, {%8,%9}, {%0,%1,%2,%3};"
        : "+f"(c[0]), "+f"(c[1]), "+f"(c[2]), "+f"(c[3])
        : "r"(a0), "r"(a1), "r"(a2), "r"(a3), "r"(b0), "r"(b1));
}

// ---------------------------------------------------------------------------
// Fused fp32 -> fp16 round over x | w1 | w2
// ---------------------------------------------------------------------------
__global__ __launch_bounds__(256)
void round_all_kernel(const float* __restrict__ x,  __half* __restrict__ xh,  int nx4,
                      const float* __restrict__ w1, __half* __restrict__ w1h, int n14,
                      const float* __restrict__ w2, __half* __restrict__ w2h, int n24)
{
    int i = blockIdx.x * 256 + threadIdx.x;
    const float* in; __half* out; int idx;
    if (i < nx4) { in = x; out = xh; idx = i; }
    else if (i < nx4 + n14) { in = w1; out = w1h; idx = i - nx4; }
    else if (i < nx4 + n14 + n24) { in = w2; out = w2h; idx = i - nx4 - n14; }
    else return;
    float4 v = ((const float4*)in)[idx];
    __half2* op = (__half2*)out;
    op[2*idx]   = __half2(__float2half_rn(v.x), __float2half_rn(v.y));
    op[2*idx+1] = __half2(__float2half_rn(v.z), __float2half_rn(v.w));
}

// ---------------------------------------------------------------------------
// HMMA fp16 GEMM: C[:, :Ntiles*128] (+ldc row stride) = A[M,K] @ B[N,K]^T.
// CTA tile 128x128, BK=64, 3-stage cp.async pipeline, 128 threads,
// warp grid 2x2, warp tile 64x64, 2 CTAs/SM. (R11 core, + ldc param.)
// ---------------------------------------------------------------------------
__global__ __launch_bounds__(GTHREADS, 2)
void gemm_hmma_kernel(const __half* __restrict__ Ah,
                      const __half* __restrict__ Bh,
                      float* __restrict__ C, int ldc, int K)
{
    extern __shared__ char smem[];
    const uint32_t sbase = smem_u32(smem);
    const int tid  = threadIdx.x;
    const int wid  = tid >> 5;
    const int lane = tid & 31;
    const int bm = blockIdx.y * BM;
    const int bn = blockIdx.x * BN;
    const int wm = (wid >> 1) * 64;
    const int wn = (wid & 1) * 64;

    const int NC = K / BKK;

    const int lrow = tid >> 3;
    const int lch  = tid & 7;
    auto load_stage = [&](int kc, int buf) {
        const uint32_t sb = sbase + buf * STAGE;
        const int k0 = kc * BKK;
#pragma unroll
        for (int j = 0; j < 8; j++) {
            int r = lrow + j * 16;
            size_t goA = (size_t)(bm + r) * K + k0 + lch * 8;
            size_t goB = (size_t)(bn + r) * K + k0 + lch * 8;
            uint32_t so = sb + r * ROWB + lch * 16;
            cp16(so,         Ah + goA);
            cp16(so + A_MAT, Bh + goB);
        }
    };

    const int lr  = lane & 7;
    const int sel = lane >> 3;
    const uint32_t a_lane_off = (uint32_t)((wm + lr + ((sel & 1) << 3)) * ROWB + ((sel >> 1) << 4));
    const uint32_t b_lane_off = (uint32_t)(A_MAT + (wn + lr + ((sel >> 1) << 3)) * ROWB + ((sel & 1) << 4));

    float acc[4][8][4];
#pragma unroll
    for (int mt = 0; mt < 4; mt++)
#pragma unroll
        for (int nt = 0; nt < 8; nt++)
#pragma unroll
            for (int r = 0; r < 4; r++) acc[mt][nt][r] = 0.f;

    load_stage(0, 0); CP_COMMIT();
    load_stage(1, 1); CP_COMMIT();

    int buf = 0;
    for (int it = 0; it < NC; it++) {
        if (it + 1 < NC) { CP_WAIT(1); } else { CP_WAIT(0); }
        __syncthreads();

        if (it + 2 < NC) { load_stage(it + 2, (buf + 2) % NSTAGE); CP_COMMIT(); }

        const uint32_t sb = sbase + buf * STAGE;
#pragma unroll
        for (int ks = 0; ks < 4; ks++) {
            const uint32_t kofs = ks * 32;
            uint32_t ah[4][4];
#pragma unroll
            for (int mt = 0; mt < 4; mt++) {
                uint32_t addr = sb + a_lane_off + mt * (16 * ROWB) + kofs;
                ldsm4(ah[mt][0], ah[mt][1], ah[mt][2], ah[mt][3], addr);
            }
#pragma unroll
            for (int ng = 0; ng < 4; ng++) {
                uint32_t bh[4];
                uint32_t addr = sb + b_lane_off + ng * (16 * ROWB) + kofs;
                ldsm4(bh[0], bh[1], bh[2], bh[3], addr);
#pragma unroll
                for (int mt = 0; mt < 4; mt++) {
#pragma unroll
                    for (int half = 0; half < 2; half++) {
                        float* a4 = acc[mt][ng * 2 + half];
                        mma16816(a4, ah[mt][0], ah[mt][1], ah[mt][2], ah[mt][3],
                                 bh[half*2], bh[half*2+1]);
                    }
                }
            }
        }
        buf = (buf + 1) % NSTAGE;
    }

    const int rrow = lane >> 2;
    const int rcol = (lane & 3) * 2;
#pragma unroll
    for (int mt = 0; mt < 4; mt++) {
        const int row0 = bm + wm + mt * 16 + rrow;
#pragma unroll
        for (int nt = 0; nt < 8; nt++) {
            const int col = bn + wn + nt * 8 + rcol;
            *(float2*)(C + (size_t)row0 * ldc + col)       = make_float2(acc[mt][nt][0], acc[mt][nt][1]);
            *(float2*)(C + (size_t)(row0 + 8) * ldc + col) = make_float2(acc[mt][nt][2], acc[mt][nt][3]);
        }
    }
}

// ---------------------------------------------------------------------------
// Conv + gates, rolling 4-t window per thread (R16 version)
// ---------------------------------------------------------------------------
__global__ __launch_bounds__(256)
void conv_gate_kernel(const float* __restrict__ cw)
{
    __shared__ float s_a[32][33];
    __shared__ float s_b[32][33];

    const int c  = blockIdx.x * 32 + threadIdx.x;
    const int fc = ((c >> 7) << 8) | (c & 127);
    const int ic = fc + 128;
    const int b  = blockIdx.z;
    const int t0 = blockIdx.y * 32;
    const int tb = t0 + threadIdx.y * 4;

    float wf[4], wi[4];
#pragma unroll
    for (int k = 0; k < 4; k++) { wf[k] = cw[fc * 4 + k]; wi[k] = cw[ic * 4 + k]; }

    const float* yf = g_y + (size_t)(b * SEQ) * FOURH + 4096 + fc;
    const float* yi = g_y + (size_t)(b * SEQ) * FOURH + 4096 + ic;
    const float* yh = g_y + (size_t)(b * SEQ) * FOURH + 2048 + c;

    float f0, f1, f2, i0, i1, i2;
    {
        int tp = tb - 3;
        f0 = (tp >= 0) ? yf[(size_t)tp * FOURH] : 0.f;
        i0 = (tp >= 0) ? yi[(size_t)tp * FOURH] : 0.f;
        tp = tb - 2;
        f1 = (tp >= 0) ? yf[(size_t)tp * FOURH] : 0.f;
        i1 = (tp >= 0) ? yi[(size_t)tp * FOURH] : 0.f;
        tp = tb - 1;
        f2 = (tp >= 0) ? yf[(size_t)tp * FOURH] : 0.f;
        i2 = (tp >= 0) ? yi[(size_t)tp * FOURH] : 0.f;
    }

#pragma unroll
    for (int j = 0; j < 4; j++) {
        const int t = tb + j;
        const float vf = yf[(size_t)t * FOURH];
        const float vi = yi[(size_t)t * FOURH];
        const float h  = yh[(size_t)t * FOURH];
        const float accf = wf[0]*f0 + wf[1]*f1 + wf[2]*f2 + wf[3]*vf;
        const float acci = wi[0]*i0 + wi[1]*i1 + wi[2]*i2 + wi[3]*vi;
        f0 = f1; f1 = f2; f2 = vf;
        i0 = i1; i1 = i2; i2 = vi;
        const float f = 1.f / (1.f + __expf(-accf));
        const float i = 1.f / (1.f + __expf(-acci));
        const float denom = 1.f / (f + i + 1e-4f);
        const int tl = threadIdx.y * 4 + j;
        s_a[tl][threadIdx.x] = f * denom;
        s_b[tl][threadIdx.x] = h * i * denom;
    }
    __syncthreads();

    const int lin = threadIdx.y * 32 + threadIdx.x;
    const int tw  = lin & 31;
    const int cb  = lin >> 5;
#pragma unroll
    for (int j = 0; j < 4; j++) {
        const int cl = cb + j * 8;
        const size_t idx = ((size_t)(b * HID + blockIdx.x * 32 + cl)) * SEQ + t0 + tw;
        g_ah[idx] = __float2half_rn(s_a[tw][cl]);
        g_bh[idx] = __float2half_rn(s_b[tw][cl]);
    }
}

// ---------------------------------------------------------------------------
// Linear scan per channel; fp16 in/out, fp32 math; warp-shuffle block scan
// ---------------------------------------------------------------------------
__global__ __launch_bounds__(128)
void scan_kernel()
{
    const int ch  = blockIdx.x;
    const int tid = threadIdx.x;
    const int lane = tid & 31;
    const int wrp  = tid >> 5;
    const size_t base = (size_t)ch * SEQ + (size_t)tid * 32;

    float a[32], bb[32];
#pragma unroll
    for (int j = 0; j < 4; j++) {
        uint4 ua = *(const uint4*)(g_ah + base + j * 8);
        uint4 ub = *(const uint4*)(g_bh + base + j * 8);
        const uint32_t* wa = (const uint32_t*)&ua;
        const uint32_t* wb = (const uint32_t*)&ub;
#pragma unroll
        for (int q = 0; q < 4; q++) {
            float2 va = __half22float2(*(const __half2*)&wa[q]);
            float2 vb = __half22float2(*(const __half2*)&wb[q]);
            a [j*8 + q*2 + 0] = va.x; a [j*8 + q*2 + 1] = va.y;
            bb[j*8 + q*2 + 0] = vb.x; bb[j*8 + q*2 + 1] = vb.y;
        }
    }

    float A = 1.f, Bv = 0.f;
#pragma unroll
    for (int j = 0; j < 32; j++) { Bv = fmaf(a[j], Bv, bb[j]); A *= a[j]; }

    float sAcc = A, sB = Bv;
#pragma unroll
    for (int off = 1; off < 32; off <<= 1) {
        float pA = __shfl_up_sync(0xFFFFFFFFu, sAcc, off);
        float pB = __shfl_up_sync(0xFFFFFFFFu, sB, off);
        if (lane >= off) { sB = fmaf(sAcc, pB, sB); sAcc *= pA; }
    }

    __shared__ float wA[4], wB[4];
    if (lane == 31) { wA[wrp] = sAcc; wB[wrp] = sB; }
    __syncthreads();
    if (tid == 0) {
        float cA = wA[0], cB = wB[0];
#pragma unroll
        for (int w = 1; w < 4; w++) {
            cB = fmaf(wA[w], cB, wB[w]);
            cA *= wA[w];
            wA[w] = cA; wB[w] = cB;
        }
    }
    __syncthreads();

    float preB;
    {
        float warpPrevB = (wrp == 0) ? 0.f : wB[wrp - 1];
        float lA = __shfl_up_sync(0xFFFFFFFFu, sAcc, 1);
        float lB = __shfl_up_sync(0xFFFFFFFFu, sB, 1);
        if (lane == 0) { lA = 1.f; lB = 0.f; }
        preB = fmaf(lA, warpPrevB, lB);
    }

    float h = preB;
    __half hout[32];
#pragma unroll
    for (int j = 0; j < 32; j++) { h = fmaf(a[j], h, bb[j]); hout[j] = __float2half_rn(h); }
#pragma unroll
    for (int j = 0; j < 4; j++)
        *(uint4*)(g_hsh + base + j * 8) = *(const uint4*)&hout[j * 8];
}

// ---------------------------------------------------------------------------
// g = silu(out1) * out2 ; reads fp16 hs, writes fp16 g
// ---------------------------------------------------------------------------
__global__ __launch_bounds__(256)
void silu_mul_kernel()
{
    __shared__ float sm[32][33];
    const int c0 = blockIdx.x * 32;
    const int s0 = blockIdx.y * 32;
    const int b  = blockIdx.z;

#pragma unroll
    for (int it = 0; it < 4; ++it) {
        const int cl = threadIdx.y + it * 8;
        const int s  = s0 + threadIdx.x;
        sm[cl][threadIdx.x] = __half2float(g_hsh[((size_t)(b * HID + c0 + cl)) * SEQ + s]);
    }
    __syncthreads();

#pragma unroll
    for (int it = 0; it < 4; ++it) {
        const int sl = threadIdx.y + it * 8;
        const int s  = s0 + sl;
        const int c  = c0 + threadIdx.x;
        const size_t row = (size_t)(b * SEQ + s);
        const float o1 = g_y[row * FOURH + c];
        const float sil = o1 / (1.f + __expf(-o1));
        const float v = sil * sm[threadIdx.x][sl];
        g_gh[row * HID + c] = __float2half_rn(v);
    }
}

// ---------------------------------------------------------------------------
// Launch — GEMM1 split: gates+h columns first (stream 0), out1 columns forked
// onto a second stream overlapping conv+scan; join before silu.
// ---------------------------------------------------------------------------
extern "C" void kernel_launch(void* const* d_in, const int* in_sizes, int n_in,
                              void* d_out, int out_size)
{
    const float* x  = (const float*)d_in[0];
    const float* w1 = (const float*)d_in[1];
    const float* w2 = (const float*)d_in[2];
    const float* cw = (const float*)d_in[3];
    float* out = (float*)d_out;

    float *yp;
    cudaGetSymbolAddress((void**)&yp, g_y);
    __half *xh, *w1h, *w2h, *gh;
    cudaGetSymbolAddress((void**)&xh,  g_xh);
    cudaGetSymbolAddress((void**)&w1h, g_w1h);
    cudaGetSymbolAddress((void**)&w2h, g_w2h);
    cudaGetSymbolAddress((void**)&gh,  g_gh);

    cudaFuncSetAttribute(gemm_hmma_kernel, cudaFuncAttributeMaxDynamicSharedMemorySize, SMEMG);

    cudaStream_t s2;
    cudaStreamCreateWithFlags(&s2, cudaStreamNonBlocking);
    cudaEvent_t e1, e2;
    cudaEventCreateWithFlags(&e1, cudaEventDisableTiming);
    cudaEventCreateWithFlags(&e2, cudaEventDisableTiming);

    // fused conversions (stream 0)
    {
        const int nx4 = MROWS * EMB / 4;
        const int n14 = FOURH * EMB / 4;
        const int n24 = EMB * HID / 4;
        const int tot = nx4 + n14 + n24;
        round_all_kernel<<<(tot + 255) / 256, 256>>>(x, xh, nx4, w1, w1h, n14, w2, w2h, n24);
    }

    // fork point: GEMM1b depends only on conversions
    cudaEventRecord(e1, 0);
    cudaStreamWaitEvent(s2, e1, 0);

    // GEMM1a (stream 0): y[:, 2048:8192] — gates + h columns
    gemm_hmma_kernel<<<dim3((FOURH - HID) / BN, MROWS / BM), GTHREADS, SMEMG>>>(
        xh, w1h + (size_t)HID * EMB, yp + HID, FOURH, EMB);

    // GEMM1b (stream s2): y[:, 0:2048] — out1 columns (overlaps conv+scan)
    gemm_hmma_kernel<<<dim3(HID / BN, MROWS / BM), GTHREADS, SMEMG, s2>>>(
        xh, w1h, yp, FOURH, EMB);
    cudaEventRecord(e2, s2);

    // conv + scan (stream 0) — depend on GEMM1a only
    conv_gate_kernel<<<dim3(HID / 32, SEQ / 32, BSZ), dim3(32, 8)>>>(cw);
    scan_kernel<<<NCH, 128>>>();

    // join: silu needs out1 (GEMM1b) + hs (scan)
    cudaStreamWaitEvent(0, e2, 0);
    silu_mul_kernel<<<dim3(HID / 32, SEQ / 32, BSZ), dim3(32, 8)>>>();

    // GEMM2: out[M,1024] = g @ w2^T
    gemm_hmma_kernel<<<dim3(EMB / BN, MROWS / BM), GTHREADS, SMEMG>>>(
        gh, w2h, out, EMB, HID);

    cudaEventDestroy(e1);
    cudaEventDestroy(e2);
    cudaStreamDestroy(s2);
}